// round 17
// baseline (speedup 1.0000x reference)
#include <cuda_runtime.h>
#include <cuda_bf16.h>
#include <stdint.h>

#define HEADS 16
#define MDIM 4096
#define NDIM 4096
#define KDIM 64
#define QBLK 32

// Quantized (dequantized-to-bf16, exact) operands. rhs stored transposed: [h][n][k].
static __device__ __nv_bfloat16 g_lhs[(size_t)HEADS * MDIM * KDIM];
static __device__ __nv_bfloat16 g_rhs[(size_t)HEADS * NDIM * KDIM];

// ===========================================================================
// Quant phase, fine-grained: 8 elements per thread (half the serial chain of
// R8's 16). Four threads share one 32-element shared-exponent block; block
// max via two shfl_xor. All arithmetic exact in fp32 (power-of-two scaling);
// results have <=8 significant bits -> exact in bf16 -> rel_err 0.
// ===========================================================================
__device__ __forceinline__ void quant8_apply(float v[8], float ma) {
    if (ma > 0.f) {
        int e = ilogbf(fmaxf(ma, 1e-38f));       // floor(log2(.)) exactly
        float scale = exp2f((float)(7 - e));     // exact power of two
        float step  = exp2f((float)(e - 7));
#pragma unroll
        for (int i = 0; i < 8; i++) {
            float q = rintf(v[i] * scale);       // round-half-even
            q = fminf(fmaxf(q, -128.f), 127.f);
            v[i] = q * step;                     // exact
        }
    } else {
#pragma unroll
        for (int i = 0; i < 8; i++) v[i] = 0.f;
    }
}

__device__ __forceinline__ uint4 pack8(const float v[8]) {
    uint32_t pk[4];
#pragma unroll
    for (int j = 0; j < 4; j++) {
        __nv_bfloat162 h2 = __floats2bfloat162_rn(v[2 * j], v[2 * j + 1]);
        pk[j] = *reinterpret_cast<uint32_t*>(&h2);
    }
    return make_uint4(pk[0], pk[1], pk[2], pk[3]);
}

// lhs: 524288 threads (4 per 32-block, consecutive -> shfl_xor 1,2). 2048 CTAs.
// rhs: 524288 threads; warp = 8 columns x one 32-k block; lanes 0-7 hold 8
//      consecutive columns, lane>>3 selects the 8-k quarter -> shfl_xor 8,16.
//      Each load instruction: 4 rows x 32B contiguous = full sectors.
#define QL_BLOCKS 2048
#define QR_BLOCKS 2048

__global__ void __launch_bounds__(256) quant_all_kernel(
    const float* __restrict__ lhs, const float* __restrict__ rhs) {
    if (blockIdx.x < QL_BLOCKS) {
        // lhs [h][m][64]: thread owns 8 consecutive floats.
        size_t t = blockIdx.x * (size_t)blockDim.x + threadIdx.x;
        const float4* src = reinterpret_cast<const float4*>(lhs + t * 8);
        float v[8];
        float4 f0 = __ldg(src), f1 = __ldg(src + 1);
        v[0] = f0.x; v[1] = f0.y; v[2] = f0.z; v[3] = f0.w;
        v[4] = f1.x; v[5] = f1.y; v[6] = f1.z; v[7] = f1.w;
        float ma = 0.f;
#pragma unroll
        for (int i = 0; i < 8; i++) ma = fmaxf(ma, fabsf(v[i]));
        ma = fmaxf(ma, __shfl_xor_sync(0xFFFFFFFFu, ma, 1));
        ma = fmaxf(ma, __shfl_xor_sync(0xFFFFFFFFu, ma, 2));  // full 32-blk max
        quant8_apply(v, ma);
        *reinterpret_cast<uint4*>(g_lhs + t * 8) = pack8(v);
    } else {
        // rhs [h][k=64][n]: warp covers 8 columns x 32 k's; transpose on write.
        int t    = (blockIdx.x - QL_BLOCKS) * blockDim.x + threadIdx.x;
        int lane = t & 31;
        int w    = t >> 5;                 // global warp id, 0..16383
        int cg   = w & 511;                // column group (8 cols each)
        int kb   = (w >> 9) & 1;           // 32-k block
        int h    = w >> 10;
        int col  = cg * 8 + (lane & 7);
        int q    = lane >> 3;              // 8-k quarter within the block
        const float* src = rhs + ((size_t)(h * KDIM + kb * QBLK + q * 8)) * NDIM + col;
        float v[8];
#pragma unroll
        for (int k = 0; k < 8; k++) v[k] = __ldg(src + (size_t)k * NDIM);
        float ma = 0.f;
#pragma unroll
        for (int i = 0; i < 8; i++) ma = fmaxf(ma, fabsf(v[i]));
        ma = fmaxf(ma, __shfl_xor_sync(0xFFFFFFFFu, ma, 8));
        ma = fmaxf(ma, __shfl_xor_sync(0xFFFFFFFFu, ma, 16)); // full 32-blk max
        quant8_apply(v, ma);
        *reinterpret_cast<uint4*>(
            g_rhs + ((size_t)h * NDIM + col) * KDIM + kb * QBLK + q * 8) = pack8(v);
    }
}

// ===========================================================================
// GEMM (R8/R16 = best measured, unchanged): out[h][m][n] = sum_k A[m][k]*B[n][k].
// CTA tile 128x128, K=64 fully resident. 8 warps = 2(m) x 4(n), warp 64x32.
// cp.async staging into XOR-swizzled 128B rows (one L1 pass), bf16
// mma.m16n8k16 with fp32 accum, __stcs streaming epilogue, 2 CTAs/SM.
// Plateau: ~5.0 TB/s effective write stream == practical HBM write ceiling.
// ===========================================================================
__global__ void __launch_bounds__(256, 2) bfp_gemm_kernel(float* __restrict__ out) {
    __shared__ __align__(128) char smem[32768];   // A: 16KB, B: 16KB
    const uint32_t sbase = (uint32_t)__cvta_generic_to_shared(smem);
    const uint32_t sB = sbase + 16384;

    const int h  = blockIdx.z;
    const int bm = blockIdx.y, bn = blockIdx.x;
    const __nv_bfloat16* gA = g_lhs + ((size_t)h * MDIM + bm * 128) * KDIM;
    const __nv_bfloat16* gB = g_rhs + ((size_t)h * NDIM + bn * 128) * KDIM;
    const int tid = threadIdx.x;

    // Stage A + B (128 rows x 128B each) via cp.async, 16B units.
    // Swizzle: unit j -> j ^ (row & 7) -> conflict-free ldmatrix phases.
#pragma unroll
    for (int i = 0; i < 4; i++) {
        int idx = i * 256 + tid;        // 0..1023 per operand
        int row = idx >> 3, j = idx & 7;
        int sw = j ^ (row & 7);
        uint32_t dstA = sbase + row * 128 + sw * 16;
        const char* srcA = reinterpret_cast<const char*>(gA + (size_t)row * KDIM) + j * 16;
        asm volatile("cp.async.cg.shared.global [%0], [%1], 16;\n" :: "r"(dstA), "l"(srcA));
        uint32_t dstB = sB + row * 128 + sw * 16;
        const char* srcB = reinterpret_cast<const char*>(gB + (size_t)row * KDIM) + j * 16;
        asm volatile("cp.async.cg.shared.global [%0], [%1], 16;\n" :: "r"(dstB), "l"(srcB));
    }
    asm volatile("cp.async.commit_group;\n" ::: "memory");
    asm volatile("cp.async.wait_group 0;\n" ::: "memory");
    __syncthreads();

    const int lane = tid & 31;
    const int wid  = tid >> 5;
    const int wm   = (wid & 1) * 64;    // 2 m-warps, warp covers 64 rows
    const int wn   = (wid >> 1) * 32;   // 4 n-warps, warp covers 32 cols
    const int g    = lane >> 2;
    const int t4   = lane & 3;

    float acc[4][4][4];
#pragma unroll
    for (int mt = 0; mt < 4; mt++)
#pragma unroll
        for (int nt = 0; nt < 4; nt++)
#pragma unroll
            for (int i = 0; i < 4; i++) acc[mt][nt][i] = 0.f;

#pragma unroll
    for (int ks = 0; ks < 4; ks++) {
        uint32_t a[4][4];
#pragma unroll
        for (int mt = 0; mt < 4; mt++) {
            int row = wm + mt * 16 + (lane & 15);
            int cu  = (ks * 2 + (lane >> 4)) ^ (row & 7);
            uint32_t addr = sbase + row * 128 + cu * 16;
            asm volatile("ldmatrix.sync.aligned.m8n8.x4.shared.b16 {%0,%1,%2,%3}, [%4];\n"
                         : "=r"(a[mt][0]), "=r"(a[mt][1]), "=r"(a[mt][2]), "=r"(a[mt][3])
                         : "r"(addr));
        }
#pragma unroll
        for (int nt = 0; nt < 4; nt++) {
            int row = wn + nt * 8 + (lane & 7);
            int cu  = (ks * 2 + ((lane >> 3) & 1)) ^ (row & 7);
            uint32_t addr = sB + row * 128 + cu * 16;
            uint32_t b0, b1;
            asm volatile("ldmatrix.sync.aligned.m8n8.x2.shared.b16 {%0,%1}, [%2];\n"
                         : "=r"(b0), "=r"(b1) : "r"(addr));
#pragma unroll
            for (int mt = 0; mt < 4; mt++) {
                asm volatile(
                    "mma.sync.aligned.m16n8k16.row.col.f32.bf16.bf16.f32 "
                    "{%0,%1,%2,%3}, {%4,%5,%6,%7}, {%8,%9}, {%0,%1,%2,%3};\n"
                    : "+f"(acc[mt][nt][0]), "+f"(acc[mt][nt][1]),
                      "+f"(acc[mt][nt][2]), "+f"(acc[mt][nt][3])
                    : "r"(a[mt][0]), "r"(a[mt][1]), "r"(a[mt][2]), "r"(a[mt][3]),
                      "r"(b0), "r"(b1));
            }
        }
    }

    // Streaming stores: 32B-sector-aligned float2 per lane, evict-first.
    float* gO = out + (size_t)h * MDIM * NDIM + (size_t)(bm * 128) * NDIM + bn * 128;
#pragma unroll
    for (int mt = 0; mt < 4; mt++) {
#pragma unroll
        for (int nt = 0; nt < 4; nt++) {
            int r0 = wm + mt * 16 + g;
            int c0 = wn + nt * 8 + t4 * 2;
            __stcs(reinterpret_cast<float2*>(&gO[(size_t)r0 * NDIM + c0]),
                   make_float2(acc[mt][nt][0], acc[mt][nt][1]));
            __stcs(reinterpret_cast<float2*>(&gO[(size_t)(r0 + 8) * NDIM + c0]),
                   make_float2(acc[mt][nt][2], acc[mt][nt][3]));
        }
    }
}

extern "C" void kernel_launch(void* const* d_in, const int* in_sizes, int n_in,
                              void* d_out, int out_size) {
    (void)in_sizes; (void)n_in; (void)out_size;
    const float* lhs = (const float*)d_in[0];  // [1,16,4096,64]
    const float* rhs = (const float*)d_in[1];  // [1,16,64,4096]
    float* out = (float*)d_out;                // [1,16,4096,4096]

    quant_all_kernel<<<QL_BLOCKS + QR_BLOCKS, 256>>>(lhs, rhs);

    dim3 grid(NDIM / 128, MDIM / 128, HEADS);
    bfp_gemm_kernel<<<grid, 256>>>(out);
}